// round 4
// baseline (speedup 1.0000x reference)
#include <cuda_runtime.h>
#include <cuda_fp16.h>
#include <cstdint>
#include <cstddef>

// ---------------- problem constants ----------------
#define BB   2
#define TT   2048
#define DD   1024
#define HH   16
#define KH   64          // D / H
#define NPJ  3088        // 3*D + H
#define MMR  4096        // B*T
#define SCALE_V 0.03125f // 1/sqrt(D)
#define CHUNK 256        // scan chunk
#define NCH   8          // T / CHUNK

// ---------------- scratch (__device__ globals; no allocations) ----------------
__device__ __half g_xh [MMR*DD];
__device__ __half g_xl [MMR*DD];
__device__ __half g_wih[NPJ*DD];
__device__ __half g_wil[NPJ*DD];
__device__ __half g_woh[DD*DD];
__device__ __half g_wol[DD*DD];
__device__ float  g_proj[MMR*NPJ];        // (B*T, 3D+H)
__device__ float  g_vbuf[MMR*DD];         // (B,H,T,K) gated v * scale
__device__ float  g_adec[BB*HH*TT];       // (B,H,T) decay multiplier
__device__ float  g_gbuf[MMR*DD];         // (B,T,D) silu(r)*y
__device__ __half g_gh [MMR*DD];
__device__ __half g_gl [MMR*DD];
__device__ float2 g_psum[BB*HH*NCH];      // partial (sum, sumsq) per group-chunk
__device__ float2 g_stats[BB*HH];         // (mean, rstd)

// ---------------- fp32 -> fp16 hi/lo split ----------------
__global__ void cvt_split_kernel(const float* __restrict__ in,
                                 __half* __restrict__ hi, __half* __restrict__ lo, int n) {
    int i = blockIdx.x * blockDim.x + threadIdx.x;
    if (i >= n) return;
    float v = in[i];
    __half h = __float2half_rn(v);
    hi[i] = h;
    lo[i] = __float2half_rn(v - __half2float(h));
}

// ---------------- fp16 mma.sync GEMM:  C[M,N] (+)= sum_pairs A[M,K] * B[N,K]^T ----------------
#define BM 128
#define BN 128
#define BK 32
#define AST 40   // padded smem row stride in halves (conflict-free for frag loads)

__global__ void __launch_bounds__(256) gemm_split_kernel(
    const __half* __restrict__ A0, const __half* __restrict__ B0,
    const __half* __restrict__ A1, const __half* __restrict__ B1,
    int npairs, float* __restrict__ C, int M, int N, int K, int doacc)
{
    __shared__ __align__(16) __half sA[2][BM*AST];
    __shared__ __align__(16) __half sB[2][BN*AST];

    const int tid  = threadIdx.x;
    const int warp = tid >> 5, lane = tid & 31;
    const int wm = warp & 3, wn = warp >> 2;      // 4 x 2 warp grid
    const int g  = lane >> 2, tg = lane & 3;      // mma group / thread-in-group
    const int bm = blockIdx.y * BM;
    const int bn = blockIdx.x * BN;
    const int KT = K / BK;
    const int total = KT * npairs;
    const int lr = tid >> 2;          // 0..63 (two rows per thread: lr, lr+64)
    const int lc = (tid & 3) * 8;     // 0,8,16,24 halves

    float accv[2][8][4];
#pragma unroll
    for (int i = 0; i < 2; i++)
#pragma unroll
        for (int j = 0; j < 8; j++)
#pragma unroll
            for (int q = 0; q < 4; q++) accv[i][j][q] = 0.f;

    uint4 av0, av1, bv0, bv1;
    const uint4 zz = make_uint4(0u, 0u, 0u, 0u);

    auto LOADG = [&](int it) {
        int pair = it / KT;
        int kk = (it - pair * KT) * BK;
        const __half* Ap = pair ? A1 : A0;
        const __half* Bp = pair ? B1 : B0;
        av0 = *(const uint4*)(Ap + (size_t)(bm + lr)      * K + kk + lc);
        av1 = *(const uint4*)(Ap + (size_t)(bm + lr + 64) * K + kk + lc);
        int n0 = bn + lr, n1 = bn + lr + 64;
        bv0 = (n0 < N) ? *(const uint4*)(Bp + (size_t)n0 * K + kk + lc) : zz;
        bv1 = (n1 < N) ? *(const uint4*)(Bp + (size_t)n1 * K + kk + lc) : zz;
    };
    auto STORES = [&](int buf) {
        *(uint4*)(sA[buf] + lr      * AST + lc) = av0;
        *(uint4*)(sA[buf] + (lr+64) * AST + lc) = av1;
        *(uint4*)(sB[buf] + lr      * AST + lc) = bv0;
        *(uint4*)(sB[buf] + (lr+64) * AST + lc) = bv1;
    };

    LOADG(0);
    STORES(0);
    __syncthreads();

    int buf = 0;
    for (int it = 0; it < total; ++it) {
        if (it + 1 < total) LOADG(it + 1);
#pragma unroll
        for (int ks = 0; ks < 2; ++ks) {
            const int ko = ks * 16 + tg * 2;
            uint32_t ra[2][4];
#pragma unroll
            for (int mi = 0; mi < 2; ++mi) {
                const __half* ab = sA[buf] + (wm*32 + mi*16 + g) * AST + ko;
                ra[mi][0] = *(const uint32_t*)(ab);
                ra[mi][1] = *(const uint32_t*)(ab + 8*AST);
                ra[mi][2] = *(const uint32_t*)(ab + 8);
                ra[mi][3] = *(const uint32_t*)(ab + 8*AST + 8);
            }
            uint32_t rb[8][2];
#pragma unroll
            for (int ni = 0; ni < 8; ++ni) {
                const __half* bb = sB[buf] + (wn*64 + ni*8 + g) * AST + ko;
                rb[ni][0] = *(const uint32_t*)(bb);
                rb[ni][1] = *(const uint32_t*)(bb + 8);
            }
#pragma unroll
            for (int mi = 0; mi < 2; ++mi)
#pragma unroll
                for (int ni = 0; ni < 8; ++ni)
                    asm volatile(
                        "mma.sync.aligned.m16n8k16.row.col.f32.f16.f16.f32 "
                        "{%0,%1,%2,%3},{%4,%5,%6,%7},{%8,%9},{%0,%1,%2,%3};\n"
                        : "+f"(accv[mi][ni][0]), "+f"(accv[mi][ni][1]),
                          "+f"(accv[mi][ni][2]), "+f"(accv[mi][ni][3])
                        : "r"(ra[mi][0]), "r"(ra[mi][1]), "r"(ra[mi][2]), "r"(ra[mi][3]),
                          "r"(rb[ni][0]), "r"(rb[ni][1]));
        }
        if (it + 1 < total) STORES(buf ^ 1);
        __syncthreads();
        buf ^= 1;
    }

#pragma unroll
    for (int mi = 0; mi < 2; ++mi) {
        int r0 = bm + wm*32 + mi*16 + g;
#pragma unroll
        for (int ni = 0; ni < 8; ++ni) {
            int c0 = bn + wn*64 + ni*8 + tg*2;
            if (c0 < N) {
                float2* p0 = (float2*)(C + (size_t)r0       * N + c0);
                float2* p1 = (float2*)(C + (size_t)(r0 + 8) * N + c0);
                float2 v0 = make_float2(accv[mi][ni][0], accv[mi][ni][1]);
                float2 v1 = make_float2(accv[mi][ni][2], accv[mi][ni][3]);
                if (doacc) {
                    float2 o0 = *p0, o1 = *p1;
                    v0.x += o0.x; v0.y += o0.y; v1.x += o1.x; v1.y += o1.y;
                }
                *p0 = v0; *p1 = v1;
            }
        }
    }
}

// ---------------- gate: shifted depthwise conv + silu gating + repack ----------------
// k_out[b,t,d] = conv_b[d] + sum_{j=0..3} conv_w[d,j] * k[b, t-6+j, d]   (zero-pad t<0)
__global__ void gate_kernel(const float* __restrict__ conv_w, const float* __restrict__ conv_b) {
    int idx = blockIdx.x * blockDim.x + threadIdx.x;
    if (idx >= MMR*DD) return;
    int d  = idx & (DD - 1);
    int bt = idx >> 10;
    int t  = bt & (TT - 1);
    int b  = bt >> 11;
    float ko = conv_b[d];
#pragma unroll
    for (int j = 0; j < 4; ++j) {
        int tt = t - 6 + j;
        if (tt >= 0)
            ko = fmaf(conv_w[d*4 + j], g_proj[(size_t)(b*TT + tt)*NPJ + 2*DD + d], ko);
    }
    float sk = ko / (1.f + __expf(-ko));                 // silu(k_out)
    float v  = g_proj[(size_t)bt*NPJ + DD + d];
    int h = d >> 6, kk = d & 63;
    g_vbuf[((size_t)(b*HH + h)*TT + t)*KH + kk] = v * sk * SCALE_V;
}

// ---------------- decay multiplier per (b,h,t) ----------------
__global__ void decay_kernel(const float* __restrict__ dp) {
    int idx = blockIdx.x * blockDim.x + threadIdx.x;
    if (idx >= BB*TT*HH) return;
    int h  = idx & (HH - 1);
    int bt = idx >> 4;
    float wv = g_proj[(size_t)bt*NPJ + 3*DD + h];
    float gg = 1.f / (1.f + expf(-(dp[h] + wv)));
    float a  = expf(-8.f * (1.f - gg) - 0.1f);           // exp(log_decay), <= exp(-0.1)
    int b = bt >> 11, t = bt & (TT - 1);
    g_adec[(b*HH + h)*TT + t] = a;
}

// ---------------- chunked scan (lookback 256; decay<=e^-0.1 => error ~7e-12)
//                  fused with silu(r)*y and GroupNorm partial sums ----------------
__global__ void scan_kernel() {
    const int c  = blockIdx.x & (NCH - 1);
    const int bh = blockIdx.x >> 3;
    const int b  = bh >> 4, h = bh & (HH - 1);
    const int k  = threadIdx.x;                          // 0..63
    const int t0 = c * CHUNK;
    int s0 = t0 - CHUNK; if (s0 < 0) s0 = 0;
    const float* vp = g_vbuf + (size_t)bh * TT * KH;
    const float* ap = g_adec + (size_t)bh * TT;
    const int col = h * KH + k;
    float y = 0.f, s1 = 0.f, s2 = 0.f;
    for (int s = s0; s < t0; ++s)                        // lookback warm-up
        y = fmaf(ap[s], y, vp[(size_t)s*KH + k]);
    for (int s = t0; s < t0 + CHUNK; ++s) {
        y = fmaf(ap[s], y, vp[(size_t)s*KH + k]);
        float r  = g_proj[(size_t)(b*TT + s)*NPJ + col];
        float sr = r / (1.f + __expf(-r));
        float gv = sr * y;
        g_gbuf[(size_t)(b*TT + s)*DD + col] = gv;
        s1 += gv;
        s2 = fmaf(gv, gv, s2);
    }
    __shared__ float rs1[64], rs2[64];
    rs1[k] = s1; rs2[k] = s2;
    __syncthreads();
    for (int off = 32; off > 0; off >>= 1) {
        if (k < off) { rs1[k] += rs1[k+off]; rs2[k] += rs2[k+off]; }
        __syncthreads();
    }
    if (k == 0) g_psum[bh*NCH + c] = make_float2(rs1[0], rs2[0]);
}

// ---------------- GroupNorm statistics (deterministic combine) ----------------
__global__ void stats_kernel() {
    int gi = threadIdx.x;
    if (gi >= BB*HH) return;
    float s1 = 0.f, s2 = 0.f;
    for (int c = 0; c < NCH; ++c) {
        float2 p = g_psum[gi*NCH + c];
        s1 += p.x; s2 += p.y;
    }
    const float inv = 1.f / (float)(KH * TT);
    float mean = s1 * inv;
    float var  = s2 * inv - mean * mean;
    g_stats[gi] = make_float2(mean, rsqrtf(var + 1e-5f));
}

// ---------------- normalize + affine + fp16 hi/lo split for GEMM2 ----------------
__global__ void normcvt_kernel(const float* __restrict__ gn_w, const float* __restrict__ gn_b) {
    int idx = blockIdx.x * blockDim.x + threadIdx.x;
    if (idx >= MMR*DD) return;
    int d  = idx & (DD - 1);
    int bt = idx >> 10;
    int b  = bt >> 11;
    int h  = d >> 6;
    float2 st = g_stats[b*HH + h];
    float val = fmaf((g_gbuf[idx] - st.x) * st.y, gn_w[d], gn_b[d]);
    __half hi = __float2half_rn(val);
    g_gh[idx] = hi;
    g_gl[idx] = __float2half_rn(val - __half2float(hi));
}

// ---------------- launch ----------------
extern "C" void kernel_launch(void* const* d_in, const int* in_sizes, int n_in,
                              void* d_out, int out_size) {
    const float* x      = (const float*)d_in[0];
    const float* W_in   = (const float*)d_in[1];
    const float* conv_w = (const float*)d_in[2];
    const float* conv_b = (const float*)d_in[3];
    const float* dp     = (const float*)d_in[4];
    const float* gn_w   = (const float*)d_in[5];
    const float* gn_b   = (const float*)d_in[6];
    const float* W_out  = (const float*)d_in[7];
    float* out = (float*)d_out;
    (void)in_sizes; (void)n_in; (void)out_size;

    void *pxh, *pxl, *pwih, *pwil, *pwoh, *pwol, *pproj, *pgh, *pgl;
    cudaGetSymbolAddress(&pxh,  g_xh);
    cudaGetSymbolAddress(&pxl,  g_xl);
    cudaGetSymbolAddress(&pwih, g_wih);
    cudaGetSymbolAddress(&pwil, g_wil);
    cudaGetSymbolAddress(&pwoh, g_woh);
    cudaGetSymbolAddress(&pwol, g_wol);
    cudaGetSymbolAddress(&pproj, g_proj);
    cudaGetSymbolAddress(&pgh,  g_gh);
    cudaGetSymbolAddress(&pgl,  g_gl);

    const int TPB = 256;
    cvt_split_kernel<<<(MMR*DD + TPB-1)/TPB, TPB>>>(x,     (__half*)pxh,  (__half*)pxl,  MMR*DD);
    cvt_split_kernel<<<(NPJ*DD + TPB-1)/TPB, TPB>>>(W_in,  (__half*)pwih, (__half*)pwil, NPJ*DD);
    cvt_split_kernel<<<(DD*DD  + TPB-1)/TPB, TPB>>>(W_out, (__half*)pwoh, (__half*)pwol, DD*DD);

    // GEMM1: proj = x @ W_in^T   (split: Ah*Bh, then Ah*Bl + Al*Bh accumulated)
    dim3 gg1((NPJ + BN - 1)/BN, MMR/BM);
    gemm_split_kernel<<<gg1, 256>>>((__half*)pxh, (__half*)pwih,
                                    (__half*)pxh, (__half*)pwih, 1,
                                    (float*)pproj, MMR, NPJ, DD, 0);
    gemm_split_kernel<<<gg1, 256>>>((__half*)pxh, (__half*)pwil,
                                    (__half*)pxl, (__half*)pwih, 2,
                                    (float*)pproj, MMR, NPJ, DD, 1);

    gate_kernel <<<(MMR*DD    + TPB-1)/TPB, TPB>>>(conv_w, conv_b);
    decay_kernel<<<(BB*TT*HH  + TPB-1)/TPB, TPB>>>(dp);
    scan_kernel <<<BB*HH*NCH, 64>>>();
    stats_kernel<<<1, 32>>>();
    normcvt_kernel<<<(MMR*DD + TPB-1)/TPB, TPB>>>(gn_w, gn_b);

    // GEMM2: out = g_norm @ W_out^T
    dim3 gg2(DD/BN, MMR/BM);
    gemm_split_kernel<<<gg2, 256>>>((__half*)pgh, (__half*)pwoh,
                                    (__half*)pgh, (__half*)pwoh, 1,
                                    out, MMR, DD, DD, 0);
    gemm_split_kernel<<<gg2, 256>>>((__half*)pgh, (__half*)pwol,
                                    (__half*)pgl, (__half*)pwoh, 2,
                                    out, MMR, DD, DD, 1);
}

// round 5
// speedup vs baseline: 1.7188x; 1.7188x over previous
#include <cuda_runtime.h>
#include <cuda_fp16.h>
#include <cstdint>
#include <cstddef>

// ---------------- problem constants ----------------
#define BB   2
#define TT   2048
#define DD   1024
#define HH   16
#define KH   64          // D / H
#define NPJ  3088        // 3*D + H
#define MMR  4096        // B*T
#define SCALE_V 0.03125f // 1/sqrt(D)
#define SCH  64          // scan chunk
#define SLB  128         // scan lookback (err <= e^-12.8 ~ 2.7e-6)
#define NCH  (TT/SCH)    // 32

// ---------------- scratch (__device__ globals; no allocations) ----------------
__device__ __half g_xh [MMR*DD];
__device__ __half g_xl [MMR*DD];
__device__ __half g_wih[NPJ*DD];
__device__ __half g_wil[NPJ*DD];
__device__ __half g_woh[DD*DD];
__device__ __half g_wol[DD*DD];
__device__ float  g_proj[(size_t)MMR*NPJ]; // (B*T, 3D+H)
__device__ float  g_vbuf[MMR*DD];          // (B,H,T,K) gated v * scale
__device__ float  g_adec[BB*HH*TT];        // (B,H,T) decay multiplier
__device__ float  g_gbuf[MMR*DD];          // (B,T,D) silu(r)*y
__device__ __half g_gh [MMR*DD];
__device__ __half g_gl [MMR*DD];
__device__ float2 g_psum[BB*HH*NCH];       // partial (sum, sumsq) per group-chunk
__device__ float2 g_stats[BB*HH];          // (mean, rstd)

// ---------------- fp32 -> fp16 hi/lo split (float4 vectorized) ----------------
__global__ void cvt_split_kernel(const float4* __restrict__ in,
                                 __half2* __restrict__ hi, __half2* __restrict__ lo, int n4) {
    int i = blockIdx.x * blockDim.x + threadIdx.x;
    if (i >= n4) return;
    float4 v = in[i];
    __half hx = __float2half_rn(v.x), hy = __float2half_rn(v.y);
    __half hz = __float2half_rn(v.z), hw = __float2half_rn(v.w);
    hi[2*i]   = __halves2half2(hx, hy);
    hi[2*i+1] = __halves2half2(hz, hw);
    lo[2*i]   = __halves2half2(__float2half_rn(v.x - __half2float(hx)),
                               __float2half_rn(v.y - __half2float(hy)));
    lo[2*i+1] = __halves2half2(__float2half_rn(v.z - __half2float(hz)),
                               __float2half_rn(v.w - __half2float(hw)));
}

// ---------------- fused 3-pass split GEMM: C = Ah*Bh^T + Ah*Bl^T + Al*Bh^T ----------------
#define BM 128
#define BN 128
#define BK 32
#define AST 40   // padded smem row stride in halves (conflict-free)

__device__ __forceinline__ void ldsm4(uint32_t& r0, uint32_t& r1, uint32_t& r2, uint32_t& r3,
                                      uint32_t addr) {
    asm volatile("ldmatrix.sync.aligned.m8n8.x4.shared.b16 {%0,%1,%2,%3}, [%4];"
                 : "=r"(r0), "=r"(r1), "=r"(r2), "=r"(r3) : "r"(addr));
}

__global__ void __launch_bounds__(256) gemm3_kernel(
    const __half* __restrict__ Ah, const __half* __restrict__ Al,
    const __half* __restrict__ Bh, const __half* __restrict__ Bl,
    float* __restrict__ C, int M, int N, int K)
{
    __shared__ __align__(16) __half sA[2][BM*AST];
    __shared__ __align__(16) __half sB[2][BN*AST];

    const int tid  = threadIdx.x;
    const int warp = tid >> 5, lane = tid & 31;
    const int wm = warp & 3, wn = warp >> 2;      // 4 x 2 warp grid
    const int g  = lane >> 2, tg = lane & 3;
    const int bm = blockIdx.y * BM;
    const int bn = blockIdx.x * BN;
    const int KT = K / BK;
    const int total = 3 * KT;
    const int lr = tid >> 2;          // 0..63
    const int lc = (tid & 3) * 8;     // 0,8,16,24 halves

    const uint32_t sAb = (uint32_t)__cvta_generic_to_shared(&sA[0][0]);
    const uint32_t sBb = (uint32_t)__cvta_generic_to_shared(&sB[0][0]);
    const uint32_t bufsz = BM * AST * 2;
    const uint32_t dA0 = (lr * AST + lc) * 2;
    const uint32_t dA1 = ((lr + 64) * AST + lc) * 2;

    const int n0 = bn + lr, n1 = bn + lr + 64;
    const int p0 = (n0 < N) ? 16 : 0;
    const int p1 = (n1 < N) ? 16 : 0;
    const size_t aoff0 = (size_t)(bm + lr) * K + lc;
    const size_t aoff1 = (size_t)(bm + lr + 64) * K + lc;
    const size_t boff0 = (size_t)((n0 < N) ? n0 : N - 1) * K + lc;
    const size_t boff1 = (size_t)((n1 < N) ? n1 : N - 1) * K + lc;

    // pass pointers: (Ah,Bh), (Ah,Bl), (Al,Bh)
    const __half* Ap = Ah;
    const __half* Bp = Bh;
    int ldk = 0, ldp = 0;

    auto ISSUE = [&](int buf) {
        const __half* a0 = Ap + aoff0 + ldk;
        const __half* a1 = Ap + aoff1 + ldk;
        const __half* b0 = Bp + boff0 + ldk;
        const __half* b1 = Bp + boff1 + ldk;
        uint32_t Ab = sAb + buf * bufsz, Bb = sBb + buf * bufsz;
        asm volatile("cp.async.cg.shared.global [%0], [%1], 16;\n" :: "r"(Ab + dA0), "l"(a0));
        asm volatile("cp.async.cg.shared.global [%0], [%1], 16;\n" :: "r"(Ab + dA1), "l"(a1));
        asm volatile("cp.async.cg.shared.global [%0], [%1], 16, %2;\n" :: "r"(Bb + dA0), "l"(b0), "r"(p0));
        asm volatile("cp.async.cg.shared.global [%0], [%1], 16, %2;\n" :: "r"(Bb + dA1), "l"(b1), "r"(p1));
        asm volatile("cp.async.commit_group;\n");
        ldk += BK;
        if (ldk == K) {
            ldk = 0; ++ldp;
            Ap = (ldp == 2) ? Al : Ah;
            Bp = (ldp == 1) ? Bl : Bh;
        }
    };

    float acc[2][8][4];
#pragma unroll
    for (int i = 0; i < 2; i++)
#pragma unroll
        for (int j = 0; j < 8; j++)
#pragma unroll
            for (int q = 0; q < 4; q++) acc[i][j][q] = 0.f;

    // ldmatrix per-lane address components
    const uint32_t a_row = wm * 32 + (lane & 15);
    const uint32_t a_ko  = (lane >> 4) << 3;
    const uint32_t b_row = wn * 64 + (lane & 7) + ((lane & 16) >> 1);
    const uint32_t b_ko  = (lane & 8);

    ISSUE(0);

    for (int it = 0; it < total; ++it) {
        const int buf = it & 1;
        if (it + 1 < total) {
            ISSUE(buf ^ 1);
            asm volatile("cp.async.wait_group 1;\n");
        } else {
            asm volatile("cp.async.wait_group 0;\n");
        }
        __syncthreads();

        const uint32_t Ab = sAb + buf * bufsz;
        const uint32_t Bb = sBb + buf * bufsz;
#pragma unroll
        for (int ks = 0; ks < 2; ++ks) {
            uint32_t ra[2][4];
#pragma unroll
            for (int mi = 0; mi < 2; ++mi) {
                uint32_t addr = Ab + ((a_row + mi * 16) * AST + ks * 16 + a_ko) * 2;
                ldsm4(ra[mi][0], ra[mi][1], ra[mi][2], ra[mi][3], addr);
            }
            uint32_t rb[8][2];
#pragma unroll
            for (int ni2 = 0; ni2 < 4; ++ni2) {
                uint32_t addr = Bb + ((b_row + ni2 * 16) * AST + ks * 16 + b_ko) * 2;
                ldsm4(rb[2*ni2][0], rb[2*ni2][1], rb[2*ni2+1][0], rb[2*ni2+1][1], addr);
            }
#pragma unroll
            for (int mi = 0; mi < 2; ++mi)
#pragma unroll
                for (int ni = 0; ni < 8; ++ni)
                    asm volatile(
                        "mma.sync.aligned.m16n8k16.row.col.f32.f16.f16.f32 "
                        "{%0,%1,%2,%3},{%4,%5,%6,%7},{%8,%9},{%0,%1,%2,%3};\n"
                        : "+f"(acc[mi][ni][0]), "+f"(acc[mi][ni][1]),
                          "+f"(acc[mi][ni][2]), "+f"(acc[mi][ni][3])
                        : "r"(ra[mi][0]), "r"(ra[mi][1]), "r"(ra[mi][2]), "r"(ra[mi][3]),
                          "r"(rb[ni][0]), "r"(rb[ni][1]));
        }
        __syncthreads();
    }

#pragma unroll
    for (int mi = 0; mi < 2; ++mi) {
        int r0 = bm + wm * 32 + mi * 16 + g;
#pragma unroll
        for (int ni = 0; ni < 8; ++ni) {
            int c0 = bn + wn * 64 + ni * 8 + tg * 2;
            if (c0 < N) {
                *(float2*)(C + (size_t)r0       * N + c0) = make_float2(acc[mi][ni][0], acc[mi][ni][1]);
                *(float2*)(C + (size_t)(r0 + 8) * N + c0) = make_float2(acc[mi][ni][2], acc[mi][ni][3]);
            }
        }
    }
}

// ---------------- gate: shifted depthwise conv + silu gating + repack (x4) ----------------
// k_out[b,t,d] = conv_b[d] + sum_{j=0..3} conv_w[d,j] * k[b, t-6+j, d]   (zero-pad t<0)
__global__ void gate_kernel(const float* __restrict__ conv_w, const float* __restrict__ conv_b) {
    int i4 = blockIdx.x * blockDim.x + threadIdx.x;
    if (i4 >= MMR * DD / 4) return;
    int idx = i4 * 4;
    int d  = idx & (DD - 1);
    int bt = idx >> 10;
    int t  = bt & (TT - 1);
    int b  = bt >> 11;

    float4 cw[4];
#pragma unroll
    for (int u = 0; u < 4; ++u) cw[u] = *(const float4*)(conv_w + (d + u) * 4);
    float4 cb = *(const float4*)(conv_b + d);
    float ko[4] = {cb.x, cb.y, cb.z, cb.w};

#pragma unroll
    for (int j = 0; j < 4; ++j) {
        int tt = t - 6 + j;
        if (tt >= 0) {
            float4 kv = *(const float4*)(g_proj + (size_t)(b * TT + tt) * NPJ + 2 * DD + d);
            ko[0] = fmaf(((const float*)&cw[0])[j], kv.x, ko[0]);
            ko[1] = fmaf(((const float*)&cw[1])[j], kv.y, ko[1]);
            ko[2] = fmaf(((const float*)&cw[2])[j], kv.z, ko[2]);
            ko[3] = fmaf(((const float*)&cw[3])[j], kv.w, ko[3]);
        }
    }
    float4 v4 = *(const float4*)(g_proj + (size_t)bt * NPJ + DD + d);
    float ov[4];
    const float* vv = (const float*)&v4;
#pragma unroll
    for (int u = 0; u < 4; ++u) {
        float sk = ko[u] / (1.f + __expf(-ko[u]));
        ov[u] = vv[u] * sk * SCALE_V;
    }
    int h = d >> 6, kk = d & 63;
    *(float4*)(g_vbuf + ((size_t)(b * HH + h) * TT + t) * KH + kk) =
        make_float4(ov[0], ov[1], ov[2], ov[3]);
}

// ---------------- decay multiplier per (b,h,t) ----------------
__global__ void decay_kernel(const float* __restrict__ dp) {
    int idx = blockIdx.x * blockDim.x + threadIdx.x;
    if (idx >= BB * TT * HH) return;
    int h  = idx & (HH - 1);
    int bt = idx >> 4;
    float wv = g_proj[(size_t)bt * NPJ + 3 * DD + h];
    float gg = 1.f / (1.f + expf(-(dp[h] + wv)));
    float a  = expf(-8.f * (1.f - gg) - 0.1f);           // exp(log_decay), <= exp(-0.1)
    int b = bt >> 11, t = bt & (TT - 1);
    g_adec[(b * HH + h) * TT + t] = a;
}

// ---------------- chunked scan, 4-way unrolled, fused silu(r)*y + GN partials ----------------
__global__ void scan_kernel() {
    const int c  = blockIdx.x & (NCH - 1);
    const int bh = blockIdx.x >> 5;
    const int b  = bh >> 4, h = bh & (HH - 1);
    const int k  = threadIdx.x;                          // 0..63
    const int t0 = c * SCH;
    int s0 = t0 - SLB; if (s0 < 0) s0 = 0;
    const float* vp = g_vbuf + (size_t)bh * TT * KH;
    const float* ap = g_adec + (size_t)bh * TT;
    const int col = h * KH + k;

    float y = 0.f;
    for (int s = s0; s < t0; s += 4) {                   // lookback warm-up
        float4 a4 = *(const float4*)(ap + s);
        float v0 = vp[(size_t)(s + 0) * KH + k];
        float v1 = vp[(size_t)(s + 1) * KH + k];
        float v2 = vp[(size_t)(s + 2) * KH + k];
        float v3 = vp[(size_t)(s + 3) * KH + k];
        y = fmaf(a4.x, y, v0);
        y = fmaf(a4.y, y, v1);
        y = fmaf(a4.z, y, v2);
        y = fmaf(a4.w, y, v3);
    }

    float s1 = 0.f, s2 = 0.f;
    for (int sm = t0; sm < t0 + SCH; sm += 4) {
        float4 a4 = *(const float4*)(ap + sm);
        float aa[4] = {a4.x, a4.y, a4.z, a4.w};
        float vv[4], rr[4];
#pragma unroll
        for (int j = 0; j < 4; ++j) {
            vv[j] = vp[(size_t)(sm + j) * KH + k];
            rr[j] = g_proj[(size_t)(b * TT + sm + j) * NPJ + col];
        }
#pragma unroll
        for (int j = 0; j < 4; ++j) {
            y = fmaf(aa[j], y, vv[j]);
            float r  = rr[j];
            float sr = r / (1.f + __expf(-r));
            float gv = sr * y;
            g_gbuf[(size_t)(b * TT + sm + j) * DD + col] = gv;
            s1 += gv;
            s2 = fmaf(gv, gv, s2);
        }
    }

    __shared__ float rs1[64], rs2[64];
    rs1[k] = s1; rs2[k] = s2;
    __syncthreads();
    for (int off = 32; off > 0; off >>= 1) {
        if (k < off) { rs1[k] += rs1[k + off]; rs2[k] += rs2[k + off]; }
        __syncthreads();
    }
    if (k == 0) g_psum[bh * NCH + c] = make_float2(rs1[0], rs2[0]);
}

// ---------------- GroupNorm statistics (deterministic combine) ----------------
__global__ void stats_kernel() {
    int gi = threadIdx.x;
    if (gi >= BB * HH) return;
    float s1 = 0.f, s2 = 0.f;
    for (int c = 0; c < NCH; ++c) {
        float2 p = g_psum[gi * NCH + c];
        s1 += p.x; s2 += p.y;
    }
    const float inv = 1.f / (float)(KH * TT);
    float mean = s1 * inv;
    float var  = s2 * inv - mean * mean;
    g_stats[gi] = make_float2(mean, rsqrtf(var + 1e-5f));
}

// ---------------- normalize + affine + fp16 hi/lo split (x4) ----------------
__global__ void normcvt_kernel(const float* __restrict__ gn_w, const float* __restrict__ gn_b) {
    int i4 = blockIdx.x * blockDim.x + threadIdx.x;
    if (i4 >= MMR * DD / 4) return;
    int idx = i4 * 4;
    int d  = idx & (DD - 1);
    int bt = idx >> 10;
    int b  = bt >> 11;
    int h  = d >> 6;
    float2 st = g_stats[b * HH + h];
    float4 gv = *(const float4*)(g_gbuf + idx);
    float4 w4 = *(const float4*)(gn_w + d);
    float4 b4 = *(const float4*)(gn_b + d);
    float vals[4];
    vals[0] = fmaf((gv.x - st.x) * st.y, w4.x, b4.x);
    vals[1] = fmaf((gv.y - st.x) * st.y, w4.y, b4.y);
    vals[2] = fmaf((gv.z - st.x) * st.y, w4.z, b4.z);
    vals[3] = fmaf((gv.w - st.x) * st.y, w4.w, b4.w);
    __half hh[4], ll[4];
#pragma unroll
    for (int u = 0; u < 4; ++u) {
        hh[u] = __float2half_rn(vals[u]);
        ll[u] = __float2half_rn(vals[u] - __half2float(hh[u]));
    }
    __half2* ph = (__half2*)(g_gh + idx);
    __half2* pl = (__half2*)(g_gl + idx);
    ph[0] = __halves2half2(hh[0], hh[1]);
    ph[1] = __halves2half2(hh[2], hh[3]);
    pl[0] = __halves2half2(ll[0], ll[1]);
    pl[1] = __halves2half2(ll[2], ll[3]);
}

// ---------------- launch ----------------
extern "C" void kernel_launch(void* const* d_in, const int* in_sizes, int n_in,
                              void* d_out, int out_size) {
    const float* x      = (const float*)d_in[0];
    const float* W_in   = (const float*)d_in[1];
    const float* conv_w = (const float*)d_in[2];
    const float* conv_b = (const float*)d_in[3];
    const float* dp     = (const float*)d_in[4];
    const float* gn_w   = (const float*)d_in[5];
    const float* gn_b   = (const float*)d_in[6];
    const float* W_out  = (const float*)d_in[7];
    float* out = (float*)d_out;
    (void)in_sizes; (void)n_in; (void)out_size;

    void *pxh, *pxl, *pwih, *pwil, *pwoh, *pwol, *pproj, *pgh, *pgl;
    cudaGetSymbolAddress(&pxh,  g_xh);
    cudaGetSymbolAddress(&pxl,  g_xl);
    cudaGetSymbolAddress(&pwih, g_wih);
    cudaGetSymbolAddress(&pwil, g_wil);
    cudaGetSymbolAddress(&pwoh, g_woh);
    cudaGetSymbolAddress(&pwol, g_wol);
    cudaGetSymbolAddress(&pproj, g_proj);
    cudaGetSymbolAddress(&pgh,  g_gh);
    cudaGetSymbolAddress(&pgl,  g_gl);

    const int TPB = 256;
    cvt_split_kernel<<<(MMR*DD/4 + TPB-1)/TPB, TPB>>>((const float4*)x,
        (__half2*)pxh, (__half2*)pxl, MMR*DD/4);
    cvt_split_kernel<<<(NPJ*DD/4 + TPB-1)/TPB, TPB>>>((const float4*)W_in,
        (__half2*)pwih, (__half2*)pwil, NPJ*DD/4);
    cvt_split_kernel<<<(DD*DD/4 + TPB-1)/TPB, TPB>>>((const float4*)W_out,
        (__half2*)pwoh, (__half2*)pwol, DD*DD/4);

    // GEMM1: proj = x @ W_in^T (fused 3-pass split)
    dim3 gg1((NPJ + BN - 1)/BN, MMR/BM);
    gemm3_kernel<<<gg1, 256>>>((__half*)pxh, (__half*)pxl,
                               (__half*)pwih, (__half*)pwil,
                               (float*)pproj, MMR, NPJ, DD);

    gate_kernel <<<(MMR*DD/4 + TPB-1)/TPB, TPB>>>(conv_w, conv_b);
    decay_kernel<<<(BB*TT*HH + TPB-1)/TPB, TPB>>>(dp);
    scan_kernel <<<BB*HH*NCH, 64>>>();
    stats_kernel<<<1, 32>>>();
    normcvt_kernel<<<(MMR*DD/4 + TPB-1)/TPB, TPB>>>(gn_w, gn_b);

    // GEMM2: out = g_norm @ W_out^T (fused 3-pass split)
    dim3 gg2(DD/BN, MMR/BM);
    gemm3_kernel<<<gg2, 256>>>((__half*)pgh, (__half*)pgl,
                               (__half*)pwoh, (__half*)pwol,
                               out, MMR, DD, DD);
}